// round 7
// baseline (speedup 1.0000x reference)
#include <cuda_runtime.h>
#include <math.h>
#include <stdint.h>

#define T_TOK 8192
#define D_DIM 1024
#define F_DIM 4096
#define E_NUM 8

// ---------------- device scratch ----------------
__device__ int   g_cnti[E_NUM];
__device__ int   g_off[E_NUM];
__device__ int   g_cursor[E_NUM];
__device__ float g_scoresum[E_NUM];
__device__ int   g_eidx[T_TOK];
__device__ float g_wgt[T_TOK];
__device__ int   g_tok[T_TOK];
__device__ float g_G[(size_t)T_TOK * F_DIM];    // GLU acts, tf32-rounded at write
__device__ float g_Xr[(size_t)T_TOK * D_DIM];   // x, tf32-rounded

// ---------------- helpers ----------------
__device__ __forceinline__ uint32_t smem_u32(const void* p) {
    uint32_t a;
    asm("{ .reg .u64 t; cvta.to.shared.u64 t, %1; cvt.u32.u64 %0, t; }" : "=r"(a) : "l"(p));
    return a;
}
__device__ __forceinline__ uint32_t cvt_tf32(float f) {
    uint32_t u; asm("cvt.rna.tf32.f32 %0, %1;" : "=r"(u) : "f"(f));
    return u;
}
__device__ __forceinline__ float tf32r(float f) {
    return __uint_as_float(cvt_tf32(f));
}
__device__ __forceinline__ void cp16(uint32_t d, const void* s) {
    asm volatile("cp.async.cg.shared.global [%0], [%1], 16;" :: "r"(d), "l"(s));
}
__device__ __forceinline__ void cp_commit() { asm volatile("cp.async.commit_group;"); }
template <int N> __device__ __forceinline__ void cp_wait() {
    asm volatile("cp.async.wait_group %0;" :: "n"(N));
}
__device__ __forceinline__ void mma8(float* c, const uint32_t* a, const uint32_t* b) {
    asm volatile(
        "mma.sync.aligned.m16n8k8.row.col.f32.tf32.tf32.f32 "
        "{%0,%1,%2,%3}, {%4,%5,%6,%7}, {%8,%9}, {%0,%1,%2,%3};"
        : "+f"(c[0]), "+f"(c[1]), "+f"(c[2]), "+f"(c[3])
        : "r"(a[0]), "r"(a[1]), "r"(a[2]), "r"(a[3]), "r"(b[0]), "r"(b[1]));
}
__device__ __forceinline__ float gelu_exact(float v) {
    return 0.5f * v * (1.0f + erff(v * 0.70710678118654752f));
}

// ---------------- stage 0: zero ----------------
__global__ void zero_kernel() {
    int i = threadIdx.x;
    if (i < E_NUM) { g_cnti[i] = 0; g_cursor[i] = 0; g_scoresum[i] = 0.0f; }
}

// ---------------- round x to tf32 ----------------
__global__ __launch_bounds__(256) void round_x_kernel(const float4* __restrict__ x) {
    size_t i = (size_t)blockIdx.x * 256 + threadIdx.x;
    float4 v = x[i];
    v.x = tf32r(v.x); v.y = tf32r(v.y); v.z = tf32r(v.z); v.w = tf32r(v.w);
    ((float4*)g_Xr)[i] = v;
}

// ---------------- stage 1: gating (fp32 exact) ----------------
__global__ __launch_bounds__(256) void gate_kernel(const float* __restrict__ x,
                                                   const float* __restrict__ Wg,
                                                   const float* __restrict__ bg) {
    int t = blockIdx.x * 8 + (threadIdx.x >> 5);
    int lane = threadIdx.x & 31;
    if (t >= T_TOK) return;
    float acc[E_NUM];
#pragma unroll
    for (int e = 0; e < E_NUM; e++) acc[e] = 0.0f;
    const float* xp = x + (size_t)t * D_DIM;
    for (int k = lane; k < D_DIM; k += 32) {
        float xv = xp[k];
        const float4 w0 = *(const float4*)(Wg + (size_t)k * E_NUM);
        const float4 w1 = *(const float4*)(Wg + (size_t)k * E_NUM + 4);
        acc[0] += xv * w0.x; acc[1] += xv * w0.y; acc[2] += xv * w0.z; acc[3] += xv * w0.w;
        acc[4] += xv * w1.x; acc[5] += xv * w1.y; acc[6] += xv * w1.z; acc[7] += xv * w1.w;
    }
#pragma unroll
    for (int e = 0; e < E_NUM; e++)
#pragma unroll
        for (int o = 16; o > 0; o >>= 1)
            acc[e] += __shfl_down_sync(0xffffffffu, acc[e], o);
    if (lane == 0) {
        float mx = -1e30f;
#pragma unroll
        for (int e = 0; e < E_NUM; e++) { acc[e] += bg[e]; mx = fmaxf(mx, acc[e]); }
        float s = 0.0f, p[E_NUM];
#pragma unroll
        for (int e = 0; e < E_NUM; e++) { p[e] = expf(acc[e] - mx); s += p[e]; }
        float inv = 1.0f / s;
        float best = -1.0f; int bi = 0;
#pragma unroll
        for (int e = 0; e < E_NUM; e++) {
            float pe = p[e] * inv;
            if (pe > best) { best = pe; bi = e; }
        }
        g_eidx[t] = bi;
        g_wgt[t] = best;
        atomicAdd(&g_scoresum[bi], best);
        atomicAdd(&g_cnti[bi], 1);
    }
}

// ---------------- stage 2: offsets + loss ----------------
__global__ void scan_loss_kernel(float* __restrict__ out, int write_loss) {
    if (threadIdx.x == 0 && blockIdx.x == 0) {
        int off = 0;
        float loss = 0.0f;
#pragma unroll
        for (int e = 0; e < E_NUM; e++) {
            g_off[e] = off;
            off += g_cnti[e];
            float usage = g_scoresum[e] / ((float)g_cnti[e] + 1e-8f);
            float d = usage - 1.0f / (float)E_NUM;
            loss += d * d;
        }
        if (write_loss) out[(size_t)T_TOK * D_DIM] = loss;
    }
}

// ---------------- stage 3: scatter ----------------
__global__ void scatter_kernel() {
    int t = blockIdx.x * blockDim.x + threadIdx.x;
    if (t >= T_TOK) return;
    int e = g_eidx[t];
    int pos = atomicAdd(&g_cursor[e], 1);
    g_tok[g_off[e] + pos] = t;
}

// ================= GEMM1: tokens[128] x (64 + 64 GLU cols), K=1024 =================
// 512 threads, 16 warps as 4m x 4n, warp tile 32 x 16 (dual B1/B2).
#define G1_A_BYTES 10240
#define G1_B_BYTES 4608
#define G1_STAGE (G1_A_BYTES + 2 * G1_B_BYTES)   // 19456
#define G1_SMEM (4 * G1_STAGE)                   // 77824

__global__ __launch_bounds__(512) void gemm1_kernel(const float* __restrict__ Wfc,
                                                    const float* __restrict__ bfc) {
    extern __shared__ __align__(128) char smem_raw[];
    uint32_t sb = smem_u32(smem_raw);
    int e = blockIdx.z;
    int cnt = g_cnti[e];
    int row0 = blockIdx.y * 128;
    if (row0 >= cnt) return;
    int col0 = blockIdx.x * 64;
    int off = g_off[e];
    int tid = threadIdx.x, wid = tid >> 5, lane = tid & 31;
    int g = lane >> 2, t4 = lane & 3;
    int wm = wid & 3, wn = wid >> 2;   // 4 x 4; warp tile 32 x 16

    // ---- loader setup: each thread does 1 A cp16 + 1 B cp16 ----
    int a_r = tid >> 2, a_c = tid & 3;
    int gi = off + row0 + a_r; if (gi > T_TOK - 1) gi = T_TOK - 1;
    const float* asrc = g_Xr + (size_t)g_tok[gi] * D_DIM + a_c * 4;
    uint32_t adst = (uint32_t)(a_r * 80 + a_c * 16);

    int bsel = tid >> 8;                 // 0 -> B1, 1 -> B2
    int bt = tid & 255;
    int b_kk = bt >> 4, b_n4 = bt & 15;
    const float* bsrc = Wfc + (size_t)e * D_DIM * (2 * F_DIM) +
                        (size_t)b_kk * (2 * F_DIM) + bsel * F_DIM + col0 + b_n4 * 4;
    uint32_t bdst = (uint32_t)(G1_A_BYTES + bsel * G1_B_BYTES + b_kk * 288 + b_n4 * 16);

#define G1_LOAD(k0, st)                                       \
    {                                                         \
        uint32_t base = sb + (uint32_t)(st) * G1_STAGE;       \
        cp16(base + adst, asrc + (k0));                       \
        cp16(base + bdst, bsrc + (size_t)(k0) * (2 * F_DIM)); \
        cp_commit();                                          \
    }

    float c1r[2][2][4], c2r[2][2][4];
#pragma unroll
    for (int mi = 0; mi < 2; mi++)
#pragma unroll
        for (int ni = 0; ni < 2; ni++)
#pragma unroll
            for (int q = 0; q < 4; q++) { c1r[mi][ni][q] = 0.0f; c2r[mi][ni][q] = 0.0f; }

    const int NCH = D_DIM / 16;  // 64
    G1_LOAD(0, 0); G1_LOAD(16, 1); G1_LOAD(32, 2);

    for (int c = 0; c < NCH; c++) {
        int st = c & 3;
        cp_wait<2>();
        __syncthreads();
        int nc = c + 3;
        if (nc < NCH) { G1_LOAD(nc * 16, nc & 3); } else { cp_commit(); }

        const uint32_t* As = (const uint32_t*)(smem_raw + st * G1_STAGE);
        const float* B1 = (const float*)(smem_raw + st * G1_STAGE + G1_A_BYTES);
        const float* B2 = (const float*)(smem_raw + st * G1_STAGE + G1_A_BYTES + G1_B_BYTES);
#pragma unroll
        for (int k8 = 0; k8 < 16; k8 += 8) {
            uint32_t af[2][4], bf1[2][2], bf2[2][2];
#pragma unroll
            for (int mi = 0; mi < 2; mi++) {
                const uint32_t* ap = As + (wm * 32 + mi * 16 + g) * 20 + k8 + t4;
                af[mi][0] = ap[0];
                af[mi][1] = ap[8 * 20];
                af[mi][2] = ap[4];
                af[mi][3] = ap[8 * 20 + 4];
            }
#pragma unroll
            for (int ni = 0; ni < 2; ni++) {
                int n = wn * 16 + ni * 8 + g;
                const float* bp1 = B1 + (k8 + t4) * 72 + n;
                bf1[ni][0] = cvt_tf32(bp1[0]);
                bf1[ni][1] = cvt_tf32(bp1[4 * 72]);
                const float* bp2 = B2 + (k8 + t4) * 72 + n;
                bf2[ni][0] = cvt_tf32(bp2[0]);
                bf2[ni][1] = cvt_tf32(bp2[4 * 72]);
            }
#pragma unroll
            for (int mi = 0; mi < 2; mi++)
#pragma unroll
                for (int ni = 0; ni < 2; ni++) {
                    mma8(c1r[mi][ni], af[mi], bf1[ni]);
                    mma8(c2r[mi][ni], af[mi], bf2[ni]);
                }
        }
    }
#undef G1_LOAD

    // epilogue: bias + GLU -> g_G (grouped rows, tf32-rounded)
    const float* bias = bfc + (size_t)e * (2 * F_DIM);
#pragma unroll
    for (int mi = 0; mi < 2; mi++) {
        int rl = wm * 32 + mi * 16 + g;
#pragma unroll
        for (int ni = 0; ni < 2; ni++) {
            int n = col0 + wn * 16 + ni * 8 + 2 * t4;
            float b1a = bias[n], b1b = bias[n + 1];
            float b2a = bias[F_DIM + n], b2b = bias[F_DIM + n + 1];
            if (row0 + rl < cnt) {
                float h1 = c1r[mi][ni][0] + b1a, h2 = c2r[mi][ni][0] + b2a;
                float u1 = c1r[mi][ni][1] + b1b, u2 = c2r[mi][ni][1] + b2b;
                float2 v = make_float2(tf32r(h1 * gelu_exact(h2)),
                                       tf32r(u1 * gelu_exact(u2)));
                *(float2*)(g_G + (size_t)(off + row0 + rl) * F_DIM + n) = v;
            }
            if (row0 + rl + 8 < cnt) {
                float h1 = c1r[mi][ni][2] + b1a, h2 = c2r[mi][ni][2] + b2a;
                float u1 = c1r[mi][ni][3] + b1b, u2 = c2r[mi][ni][3] + b2b;
                float2 v = make_float2(tf32r(h1 * gelu_exact(h2)),
                                       tf32r(u1 * gelu_exact(u2)));
                *(float2*)(g_G + (size_t)(off + row0 + rl + 8) * F_DIM + n) = v;
            }
        }
    }
}

// ================= GEMM2: rows[128] x 64 D cols, K=4096 =================
#define G2_A_BYTES 10240
#define G2_B_BYTES 4608
#define G2_STAGE (G2_A_BYTES + G2_B_BYTES)   // 14848
#define G2_SMEM (4 * G2_STAGE)               // 59392

__global__ __launch_bounds__(512) void gemm2_kernel(const float* __restrict__ Wout,
                                                    const float* __restrict__ bout,
                                                    float* __restrict__ out) {
    extern __shared__ __align__(128) char smem_raw[];
    uint32_t sb = smem_u32(smem_raw);
    int e = blockIdx.z;
    int cnt = g_cnti[e];
    int row0 = blockIdx.y * 128;
    if (row0 >= cnt) return;
    int col0 = blockIdx.x * 64;
    int off = g_off[e];
    int tid = threadIdx.x, wid = tid >> 5, lane = tid & 31;
    int g = lane >> 2, t4 = lane & 3;
    int wm = wid & 3, wn = wid >> 2;

    int a_r = tid >> 2, a_c = tid & 3;
    int gia = off + row0 + a_r; if (gia > T_TOK - 1) gia = T_TOK - 1;
    const float* asrc = g_G + (size_t)gia * F_DIM + a_c * 4;
    uint32_t adst = (uint32_t)(a_r * 80 + a_c * 16);

    int bt = tid & 255;
    int b_kk = bt >> 4, b_n4 = bt & 15;
    const float* bsrc = Wout + (size_t)e * F_DIM * D_DIM +
                        (size_t)b_kk * D_DIM + col0 + b_n4 * 4;
    uint32_t bdst = (uint32_t)(G2_A_BYTES + b_kk * 288 + b_n4 * 16);
    bool bload = tid < 256;

#define G2_LOAD(k0, st)                                                   \
    {                                                                     \
        uint32_t base = sb + (uint32_t)(st) * G2_STAGE;                   \
        cp16(base + adst, asrc + (k0));                                   \
        if (bload) cp16(base + bdst, bsrc + (size_t)(k0) * D_DIM);        \
        cp_commit();                                                      \
    }

    float cr[2][2][4];
#pragma unroll
    for (int mi = 0; mi < 2; mi++)
#pragma unroll
        for (int ni = 0; ni < 2; ni++)
#pragma unroll
            for (int q = 0; q < 4; q++) cr[mi][ni][q] = 0.0f;

    const int NCH = F_DIM / 16;  // 256
    G2_LOAD(0, 0); G2_LOAD(16, 1); G2_LOAD(32, 2);

    for (int c = 0; c < NCH; c++) {
        int st = c & 3;
        cp_wait<2>();
        __syncthreads();
        int nc = c + 3;
        if (nc < NCH) { G2_LOAD(nc * 16, nc & 3); } else { cp_commit(); }

        const uint32_t* As = (const uint32_t*)(smem_raw + st * G2_STAGE);
        const float* Bs = (const float*)(smem_raw + st * G2_STAGE + G2_A_BYTES);
#pragma unroll
        for (int k8 = 0; k8 < 16; k8 += 8) {
            uint32_t af[2][4], bf[2][2];
#pragma unroll
            for (int mi = 0; mi < 2; mi++) {
                const uint32_t* ap = As + (wm * 32 + mi * 16 + g) * 20 + k8 + t4;
                af[mi][0] = ap[0];
                af[mi][1] = ap[8 * 20];
                af[mi][2] = ap[4];
                af[mi][3] = ap[8 * 20 + 4];
            }
#pragma unroll
            for (int ni = 0; ni < 2; ni++) {
                int n = wn * 16 + ni * 8 + g;
                const float* bp = Bs + (k8 + t4) * 72 + n;
                bf[ni][0] = cvt_tf32(bp[0]);
                bf[ni][1] = cvt_tf32(bp[4 * 72]);
            }
#pragma unroll
            for (int mi = 0; mi < 2; mi++)
#pragma unroll
                for (int ni = 0; ni < 2; ni++)
                    mma8(cr[mi][ni], af[mi], bf[ni]);
        }
    }
#undef G2_LOAD

    const float* bias = bout + (size_t)e * D_DIM;
#pragma unroll
    for (int mi = 0; mi < 2; mi++) {
        int rl = wm * 32 + mi * 16 + g;
#pragma unroll
        for (int ni = 0; ni < 2; ni++) {
            int n = col0 + wn * 16 + ni * 8 + 2 * t4;
            float ba = bias[n], bb = bias[n + 1];
            if (row0 + rl < cnt) {
                int tok = g_tok[off + row0 + rl];
                float w = g_wgt[tok];
                float2 v = make_float2(w * (cr[mi][ni][0] + ba),
                                       w * (cr[mi][ni][1] + bb));
                *(float2*)(out + (size_t)tok * D_DIM + n) = v;
            }
            if (row0 + rl + 8 < cnt) {
                int tok = g_tok[off + row0 + rl + 8];
                float w = g_wgt[tok];
                float2 v = make_float2(w * (cr[mi][ni][2] + ba),
                                       w * (cr[mi][ni][3] + bb));
                *(float2*)(out + (size_t)tok * D_DIM + n) = v;
            }
        }
    }
}

// ---------------- launch ----------------
extern "C" void kernel_launch(void* const* d_in, const int* in_sizes, int n_in,
                              void* d_out, int out_size) {
    const float* x    = (const float*)d_in[0];
    const float* Wg   = (const float*)d_in[1];
    const float* bg   = (const float*)d_in[2];
    const float* Wfc  = (const float*)d_in[3];
    const float* bfc  = (const float*)d_in[4];
    const float* Wout = (const float*)d_in[5];
    const float* bout = (const float*)d_in[6];
    float* out = (float*)d_out;
    int write_loss = (out_size > T_TOK * D_DIM) ? 1 : 0;

    cudaFuncSetAttribute(gemm1_kernel, cudaFuncAttributeMaxDynamicSharedMemorySize, G1_SMEM);
    cudaFuncSetAttribute(gemm2_kernel, cudaFuncAttributeMaxDynamicSharedMemorySize, G2_SMEM);

    zero_kernel<<<1, 32>>>();
    round_x_kernel<<<T_TOK * D_DIM / 1024, 256>>>((const float4*)x);
    gate_kernel<<<T_TOK / 8, 256>>>(x, Wg, bg);
    scan_loss_kernel<<<1, 32>>>(out, write_loss);
    scatter_kernel<<<T_TOK / 256, 256>>>();
    {
        dim3 grid(F_DIM / 64, T_TOK / 128, E_NUM);
        gemm1_kernel<<<grid, 512, G1_SMEM>>>(Wfc, bfc);
    }
    {
        dim3 grid(D_DIM / 64, T_TOK / 128, E_NUM);
        gemm2_kernel<<<grid, 512, G2_SMEM>>>(Wout, bout, out);
    }
}

// round 8
// speedup vs baseline: 1.0431x; 1.0431x over previous
#include <cuda_runtime.h>
#include <math.h>
#include <stdint.h>

#define T_TOK 8192
#define D_DIM 1024
#define F_DIM 4096
#define E_NUM 8

// ---------------- device scratch ----------------
__device__ int   g_cnti[E_NUM];
__device__ int   g_off[E_NUM];
__device__ int   g_cursor[E_NUM];
__device__ int   g_eidx[T_TOK];
__device__ float g_wgt[T_TOK];
__device__ int   g_tok[T_TOK];
__device__ float g_G[(size_t)T_TOK * F_DIM];    // GLU acts, tf32-rounded at write
__device__ float g_Xr[(size_t)T_TOK * D_DIM];   // x, tf32-rounded (written by gate)

// ---------------- helpers ----------------
__device__ __forceinline__ uint32_t smem_u32(const void* p) {
    uint32_t a;
    asm("{ .reg .u64 t; cvta.to.shared.u64 t, %1; cvt.u32.u64 %0, t; }" : "=r"(a) : "l"(p));
    return a;
}
__device__ __forceinline__ uint32_t cvt_tf32(float f) {
    uint32_t u; asm("cvt.rna.tf32.f32 %0, %1;" : "=r"(u) : "f"(f));
    return u;
}
__device__ __forceinline__ float tf32r(float f) {
    return __uint_as_float(cvt_tf32(f));
}
__device__ __forceinline__ void cp16(uint32_t d, const void* s) {
    asm volatile("cp.async.cg.shared.global [%0], [%1], 16;" :: "r"(d), "l"(s));
}
__device__ __forceinline__ void cp_commit() { asm volatile("cp.async.commit_group;"); }
template <int N> __device__ __forceinline__ void cp_wait() {
    asm volatile("cp.async.wait_group %0;" :: "n"(N));
}
__device__ __forceinline__ void mma8(float* c, const uint32_t* a, const uint32_t* b) {
    asm volatile(
        "mma.sync.aligned.m16n8k8.row.col.f32.tf32.tf32.f32 "
        "{%0,%1,%2,%3}, {%4,%5,%6,%7}, {%8,%9}, {%0,%1,%2,%3};"
        : "+f"(c[0]), "+f"(c[1]), "+f"(c[2]), "+f"(c[3])
        : "r"(a[0]), "r"(a[1]), "r"(a[2]), "r"(a[3]), "r"(b[0]), "r"(b[1]));
}
__device__ __forceinline__ float gelu_exact(float v) {
    return 0.5f * v * (1.0f + erff(v * 0.70710678118654752f));
}

// ---------------- launch 1: gating (fp32 exact) + tf32-round x ----------------
__global__ __launch_bounds__(256) void gate_kernel(const float* __restrict__ x,
                                                   const float* __restrict__ Wg,
                                                   const float* __restrict__ bg) {
    int t = blockIdx.x * 8 + (threadIdx.x >> 5);
    int lane = threadIdx.x & 31;
    if (t >= T_TOK) return;
    float acc[E_NUM];
#pragma unroll
    for (int e = 0; e < E_NUM; e++) acc[e] = 0.0f;
    const float* xp = x + (size_t)t * D_DIM;
    float* xr = g_Xr + (size_t)t * D_DIM;
    for (int k = lane; k < D_DIM; k += 32) {
        float xv = xp[k];
        xr[k] = tf32r(xv);                       // fused tf32 rounding pass
        const float4 w0 = *(const float4*)(Wg + (size_t)k * E_NUM);
        const float4 w1 = *(const float4*)(Wg + (size_t)k * E_NUM + 4);
        acc[0] += xv * w0.x; acc[1] += xv * w0.y; acc[2] += xv * w0.z; acc[3] += xv * w0.w;
        acc[4] += xv * w1.x; acc[5] += xv * w1.y; acc[6] += xv * w1.z; acc[7] += xv * w1.w;
    }
#pragma unroll
    for (int e = 0; e < E_NUM; e++)
#pragma unroll
        for (int o = 16; o > 0; o >>= 1)
            acc[e] += __shfl_down_sync(0xffffffffu, acc[e], o);
    if (lane == 0) {
        float mx = -1e30f;
#pragma unroll
        for (int e = 0; e < E_NUM; e++) { acc[e] += bg[e]; mx = fmaxf(mx, acc[e]); }
        float s = 0.0f, p[E_NUM];
#pragma unroll
        for (int e = 0; e < E_NUM; e++) { p[e] = expf(acc[e] - mx); s += p[e]; }
        float inv = 1.0f / s;
        float best = -1.0f; int bi = 0;
#pragma unroll
        for (int e = 0; e < E_NUM; e++) {
            float pe = p[e] * inv;
            if (pe > best) { best = pe; bi = e; }
        }
        g_eidx[t] = bi;
        g_wgt[t] = best;
    }
}

// ---------------- launch 2: counts + offsets + loss (one block) ----------------
__global__ __launch_bounds__(256) void count_scan_kernel(float* __restrict__ out,
                                                         int write_loss) {
    __shared__ int cnt[E_NUM];
    __shared__ float ssum[E_NUM];
    int tid = threadIdx.x;
    if (tid < E_NUM) { cnt[tid] = 0; ssum[tid] = 0.0f; }
    __syncthreads();
    for (int t = tid; t < T_TOK; t += 256) {
        int e = g_eidx[t];
        atomicAdd(&cnt[e], 1);
        atomicAdd(&ssum[e], g_wgt[t]);
    }
    __syncthreads();
    if (tid == 0) {
        int off = 0;
        float loss = 0.0f;
#pragma unroll
        for (int e = 0; e < E_NUM; e++) {
            g_cnti[e] = cnt[e];
            g_off[e] = off;
            g_cursor[e] = 0;
            off += cnt[e];
            float usage = ssum[e] / ((float)cnt[e] + 1e-8f);
            float d = usage - 1.0f / (float)E_NUM;
            loss += d * d;
        }
        if (write_loss) out[(size_t)T_TOK * D_DIM] = loss;
    }
}

// ---------------- launch 3: scatter ----------------
__global__ void scatter_kernel() {
    int t = blockIdx.x * blockDim.x + threadIdx.x;
    if (t >= T_TOK) return;
    int e = g_eidx[t];
    int pos = atomicAdd(&g_cursor[e], 1);
    g_tok[g_off[e] + pos] = t;
}

// ================= launch 4: GEMM1 tokens[128] x (64 + 64 GLU cols), K=1024 =================
// 256 threads, 8 warps as 2m x 4n, warp tile 64 x 16 (dual B1/B2). A pre-rounded (no cvt).
#define G1_A_BYTES 10240
#define G1_B_BYTES 4608
#define G1_STAGE (G1_A_BYTES + 2 * G1_B_BYTES)   // 19456
#define G1_SMEM (4 * G1_STAGE)                   // 77824

__global__ __launch_bounds__(256) void gemm1_kernel(const float* __restrict__ Wfc,
                                                    const float* __restrict__ bfc) {
    extern __shared__ __align__(128) char smem_raw[];
    uint32_t sb = smem_u32(smem_raw);
    int e = blockIdx.z;
    int cnt = g_cnti[e];
    int row0 = blockIdx.y * 128;
    if (row0 >= cnt) return;
    int col0 = blockIdx.x * 64;
    int off = g_off[e];
    int tid = threadIdx.x, wid = tid >> 5, lane = tid & 31;
    int g = lane >> 2, t4 = lane & 3;
    int wm = wid & 1, wn = wid >> 1;   // 2 x 4 warp grid; warp tile 64 x 16

    // A loaders: ids tid, tid+256
    int a_r0 = tid >> 2,         a_c0 = tid & 3;
    int a_r1 = (tid + 256) >> 2, a_c1 = (tid + 256) & 3;
    int gi0 = off + row0 + a_r0; if (gi0 > T_TOK - 1) gi0 = T_TOK - 1;
    int gi1 = off + row0 + a_r1; if (gi1 > T_TOK - 1) gi1 = T_TOK - 1;
    const float* asrc0 = g_Xr + (size_t)g_tok[gi0] * D_DIM + a_c0 * 4;
    const float* asrc1 = g_Xr + (size_t)g_tok[gi1] * D_DIM + a_c1 * 4;
    uint32_t adst0 = (uint32_t)(a_r0 * 80 + a_c0 * 16);
    uint32_t adst1 = (uint32_t)(a_r1 * 80 + a_c1 * 16);
    // B loaders
    int b_kk = tid >> 4, b_n4 = tid & 15;
    const float* bbase = Wfc + (size_t)e * D_DIM * (2 * F_DIM) +
                         (size_t)b_kk * (2 * F_DIM) + col0 + b_n4 * 4;
    uint32_t bdst = (uint32_t)(b_kk * 288 + b_n4 * 16);

#define G1_LOAD(k0, st)                                                       \
    {                                                                         \
        uint32_t base = sb + (uint32_t)(st) * G1_STAGE;                       \
        cp16(base + adst0, asrc0 + (k0));                                     \
        cp16(base + adst1, asrc1 + (k0));                                     \
        const float* bp = bbase + (size_t)(k0) * (2 * F_DIM);                 \
        cp16(base + G1_A_BYTES + bdst, bp);                                   \
        cp16(base + G1_A_BYTES + G1_B_BYTES + bdst, bp + F_DIM);              \
        cp_commit();                                                          \
    }

    float c1r[4][2][4], c2r[4][2][4];
#pragma unroll
    for (int mi = 0; mi < 4; mi++)
#pragma unroll
        for (int ni = 0; ni < 2; ni++)
#pragma unroll
            for (int q = 0; q < 4; q++) { c1r[mi][ni][q] = 0.0f; c2r[mi][ni][q] = 0.0f; }

    const int NCH = D_DIM / 16;  // 64
    G1_LOAD(0, 0); G1_LOAD(16, 1); G1_LOAD(32, 2);

    for (int c = 0; c < NCH; c++) {
        int st = c & 3;
        cp_wait<2>();
        __syncthreads();
        int nc = c + 3;
        if (nc < NCH) { G1_LOAD(nc * 16, nc & 3); } else { cp_commit(); }

        const uint32_t* As = (const uint32_t*)(smem_raw + st * G1_STAGE);
        const float* B1 = (const float*)(smem_raw + st * G1_STAGE + G1_A_BYTES);
        const float* B2 = (const float*)(smem_raw + st * G1_STAGE + G1_A_BYTES + G1_B_BYTES);
#pragma unroll
        for (int k8 = 0; k8 < 16; k8 += 8) {
            uint32_t af[4][4], bf1[2][2], bf2[2][2];
#pragma unroll
            for (int mi = 0; mi < 4; mi++) {
                const uint32_t* ap = As + (wm * 64 + mi * 16 + g) * 20 + k8 + t4;
                af[mi][0] = ap[0];
                af[mi][1] = ap[8 * 20];
                af[mi][2] = ap[4];
                af[mi][3] = ap[8 * 20 + 4];
            }
#pragma unroll
            for (int ni = 0; ni < 2; ni++) {
                int n = wn * 16 + ni * 8 + g;
                const float* bp1 = B1 + (k8 + t4) * 72 + n;
                bf1[ni][0] = cvt_tf32(bp1[0]);
                bf1[ni][1] = cvt_tf32(bp1[4 * 72]);
                const float* bp2 = B2 + (k8 + t4) * 72 + n;
                bf2[ni][0] = cvt_tf32(bp2[0]);
                bf2[ni][1] = cvt_tf32(bp2[4 * 72]);
            }
#pragma unroll
            for (int mi = 0; mi < 4; mi++)
#pragma unroll
                for (int ni = 0; ni < 2; ni++) {
                    mma8(c1r[mi][ni], af[mi], bf1[ni]);
                    mma8(c2r[mi][ni], af[mi], bf2[ni]);
                }
        }
    }
#undef G1_LOAD

    // epilogue: bias + GLU -> g_G (grouped rows, tf32-rounded)
    const float* bias = bfc + (size_t)e * (2 * F_DIM);
#pragma unroll
    for (int mi = 0; mi < 4; mi++) {
        int rl = wm * 64 + mi * 16 + g;
#pragma unroll
        for (int ni = 0; ni < 2; ni++) {
            int n = col0 + wn * 16 + ni * 8 + 2 * t4;
            float b1a = bias[n], b1b = bias[n + 1];
            float b2a = bias[F_DIM + n], b2b = bias[F_DIM + n + 1];
            if (row0 + rl < cnt) {
                float h1 = c1r[mi][ni][0] + b1a, h2 = c2r[mi][ni][0] + b2a;
                float u1 = c1r[mi][ni][1] + b1b, u2 = c2r[mi][ni][1] + b2b;
                float2 v = make_float2(tf32r(h1 * gelu_exact(h2)),
                                       tf32r(u1 * gelu_exact(u2)));
                *(float2*)(g_G + (size_t)(off + row0 + rl) * F_DIM + n) = v;
            }
            if (row0 + rl + 8 < cnt) {
                float h1 = c1r[mi][ni][2] + b1a, h2 = c2r[mi][ni][2] + b2a;
                float u1 = c1r[mi][ni][3] + b1b, u2 = c2r[mi][ni][3] + b2b;
                float2 v = make_float2(tf32r(h1 * gelu_exact(h2)),
                                       tf32r(u1 * gelu_exact(u2)));
                *(float2*)(g_G + (size_t)(off + row0 + rl + 8) * F_DIM + n) = v;
            }
        }
    }
}

// ================= launch 5: GEMM2 rows[128] x 64 D cols, K=4096 =================
#define G2_A_BYTES 10240
#define G2_B_BYTES 4608
#define G2_STAGE (G2_A_BYTES + G2_B_BYTES)   // 14848
#define G2_SMEM (4 * G2_STAGE)               // 59392

__global__ __launch_bounds__(256) void gemm2_kernel(const float* __restrict__ Wout,
                                                    const float* __restrict__ bout,
                                                    float* __restrict__ out) {
    extern __shared__ __align__(128) char smem_raw[];
    uint32_t sb = smem_u32(smem_raw);
    int e = blockIdx.z;
    int cnt = g_cnti[e];
    int row0 = blockIdx.y * 128;
    if (row0 >= cnt) return;
    int col0 = blockIdx.x * 64;
    int off = g_off[e];
    int tid = threadIdx.x, wid = tid >> 5, lane = tid & 31;
    int g = lane >> 2, t4 = lane & 3;
    int wm = wid & 1, wn = wid >> 1;

    int a_r0 = tid >> 2,         a_c0 = tid & 3;
    int a_r1 = (tid + 256) >> 2, a_c1 = (tid + 256) & 3;
    int gi0 = off + row0 + a_r0; if (gi0 > T_TOK - 1) gi0 = T_TOK - 1;
    int gi1 = off + row0 + a_r1; if (gi1 > T_TOK - 1) gi1 = T_TOK - 1;
    const float* asrc0 = g_G + (size_t)gi0 * F_DIM + a_c0 * 4;
    const float* asrc1 = g_G + (size_t)gi1 * F_DIM + a_c1 * 4;
    uint32_t adst0 = (uint32_t)(a_r0 * 80 + a_c0 * 16);
    uint32_t adst1 = (uint32_t)(a_r1 * 80 + a_c1 * 16);
    int b_kk = tid >> 4, b_n4 = tid & 15;
    const float* bbase = Wout + (size_t)e * F_DIM * D_DIM +
                         (size_t)b_kk * D_DIM + col0 + b_n4 * 4;
    uint32_t bdst = (uint32_t)(b_kk * 288 + b_n4 * 16);

#define G2_LOAD(k0, st)                                       \
    {                                                         \
        uint32_t base = sb + (uint32_t)(st) * G2_STAGE;       \
        cp16(base + adst0, asrc0 + (k0));                     \
        cp16(base + adst1, asrc1 + (k0));                     \
        cp16(base + G2_A_BYTES + bdst, bbase + (size_t)(k0) * D_DIM); \
        cp_commit();                                          \
    }

    float cr[4][2][4];
#pragma unroll
    for (int mi = 0; mi < 4; mi++)
#pragma unroll
        for (int ni = 0; ni < 2; ni++)
#pragma unroll
            for (int q = 0; q < 4; q++) cr[mi][ni][q] = 0.0f;

    const int NCH = F_DIM / 16;  // 256
    G2_LOAD(0, 0); G2_LOAD(16, 1); G2_LOAD(32, 2);

    for (int c = 0; c < NCH; c++) {
        int st = c & 3;
        cp_wait<2>();
        __syncthreads();
        int nc = c + 3;
        if (nc < NCH) { G2_LOAD(nc * 16, nc & 3); } else { cp_commit(); }

        const uint32_t* As = (const uint32_t*)(smem_raw + st * G2_STAGE);
        const float* Bs = (const float*)(smem_raw + st * G2_STAGE + G2_A_BYTES);
#pragma unroll
        for (int k8 = 0; k8 < 16; k8 += 8) {
            uint32_t af[4][4], bf[2][2];
#pragma unroll
            for (int mi = 0; mi < 4; mi++) {
                const uint32_t* ap = As + (wm * 64 + mi * 16 + g) * 20 + k8 + t4;
                af[mi][0] = ap[0];
                af[mi][1] = ap[8 * 20];
                af[mi][2] = ap[4];
                af[mi][3] = ap[8 * 20 + 4];
            }
#pragma unroll
            for (int ni = 0; ni < 2; ni++) {
                int n = wn * 16 + ni * 8 + g;
                const float* bp = Bs + (k8 + t4) * 72 + n;
                bf[ni][0] = cvt_tf32(bp[0]);
                bf[ni][1] = cvt_tf32(bp[4 * 72]);
            }
#pragma unroll
            for (int mi = 0; mi < 4; mi++)
#pragma unroll
                for (int ni = 0; ni < 2; ni++)
                    mma8(cr[mi][ni], af[mi], bf[ni]);
        }
    }
#undef G2_LOAD

    const float* bias = bout + (size_t)e * D_DIM;
#pragma unroll
    for (int mi = 0; mi < 4; mi++) {
        int rl = wm * 64 + mi * 16 + g;
#pragma unroll
        for (int ni = 0; ni < 2; ni++) {
            int n = col0 + wn * 16 + ni * 8 + 2 * t4;
            float ba = bias[n], bb = bias[n + 1];
            if (row0 + rl < cnt) {
                int tok = g_tok[off + row0 + rl];
                float w = g_wgt[tok];
                float2 v = make_float2(w * (cr[mi][ni][0] + ba),
                                       w * (cr[mi][ni][1] + bb));
                *(float2*)(out + (size_t)tok * D_DIM + n) = v;
            }
            if (row0 + rl + 8 < cnt) {
                int tok = g_tok[off + row0 + rl + 8];
                float w = g_wgt[tok];
                float2 v = make_float2(w * (cr[mi][ni][2] + ba),
                                       w * (cr[mi][ni][3] + bb));
                *(float2*)(out + (size_t)tok * D_DIM + n) = v;
            }
        }
    }
}

// ---------------- launch ----------------
extern "C" void kernel_launch(void* const* d_in, const int* in_sizes, int n_in,
                              void* d_out, int out_size) {
    const float* x    = (const float*)d_in[0];
    const float* Wg   = (const float*)d_in[1];
    const float* bg   = (const float*)d_in[2];
    const float* Wfc  = (const float*)d_in[3];
    const float* bfc  = (const float*)d_in[4];
    const float* Wout = (const float*)d_in[5];
    const float* bout = (const float*)d_in[6];
    float* out = (float*)d_out;
    int write_loss = (out_size > T_TOK * D_DIM) ? 1 : 0;

    cudaFuncSetAttribute(gemm1_kernel, cudaFuncAttributeMaxDynamicSharedMemorySize, G1_SMEM);
    cudaFuncSetAttribute(gemm2_kernel, cudaFuncAttributeMaxDynamicSharedMemorySize, G2_SMEM);

    gate_kernel<<<T_TOK / 8, 256>>>(x, Wg, bg);          // launch 1
    count_scan_kernel<<<1, 256>>>(out, write_loss);      // launch 2
    scatter_kernel<<<T_TOK / 256, 256>>>();              // launch 3
    {
        dim3 grid(F_DIM / 64, T_TOK / 128, E_NUM);
        gemm1_kernel<<<grid, 256, G1_SMEM>>>(Wfc, bfc);  // launch 4 (profiled)
    }
    {
        dim3 grid(D_DIM / 64, T_TOK / 128, E_NUM);
        gemm2_kernel<<<grid, 256, G2_SMEM>>>(Wout, bout, out);  // launch 5
    }
}

// round 9
// speedup vs baseline: 1.1694x; 1.1211x over previous
#include <cuda_runtime.h>
#include <math.h>
#include <stdint.h>

#define T_TOK 8192
#define D_DIM 1024
#define F_DIM 4096
#define E_NUM 8

// ---------------- device scratch ----------------
__device__ int   g_cnti[E_NUM];
__device__ int   g_off[E_NUM];
__device__ int   g_cursor[E_NUM];
__device__ int   g_eidx[T_TOK];
__device__ float g_wgt[T_TOK];
__device__ int   g_tok[T_TOK];
__device__ float g_G[(size_t)T_TOK * F_DIM];    // GLU acts, tf32-rounded, PERMUTED k-layout
__device__ float g_Xr[(size_t)T_TOK * D_DIM];   // x, tf32-rounded, PERMUTED k-layout

// in-8-group permutation: k -> pos so that (k, k+4) land adjacent
__device__ __forceinline__ int perm8(int k) {
    return (k & ~7) | (((k & 3) << 1) | ((k >> 2) & 1));
}

// ---------------- helpers ----------------
__device__ __forceinline__ uint32_t cvt_tf32(float f) {
    uint32_t u; asm("cvt.rna.tf32.f32 %0, %1;" : "=r"(u) : "f"(f));
    return u;
}
__device__ __forceinline__ float tf32r(float f) {
    return __uint_as_float(cvt_tf32(f));
}
__device__ __forceinline__ uint32_t smem_u32(const void* p) {
    uint32_t a;
    asm("{ .reg .u64 t; cvta.to.shared.u64 t, %1; cvt.u32.u64 %0, t; }" : "=r"(a) : "l"(p));
    return a;
}
__device__ __forceinline__ void cp16(uint32_t d, const void* s) {
    asm volatile("cp.async.cg.shared.global [%0], [%1], 16;" :: "r"(d), "l"(s));
}
__device__ __forceinline__ void cp_commit() { asm volatile("cp.async.commit_group;"); }
template <int N> __device__ __forceinline__ void cp_wait() {
    asm volatile("cp.async.wait_group %0;" :: "n"(N));
}
__device__ __forceinline__ void mma8(float* c, const uint32_t* a, const uint32_t* b) {
    asm volatile(
        "mma.sync.aligned.m16n8k8.row.col.f32.tf32.tf32.f32 "
        "{%0,%1,%2,%3}, {%4,%5,%6,%7}, {%8,%9}, {%0,%1,%2,%3};"
        : "+f"(c[0]), "+f"(c[1]), "+f"(c[2]), "+f"(c[3])
        : "r"(a[0]), "r"(a[1]), "r"(a[2]), "r"(a[3]), "r"(b[0]), "r"(b[1]));
}
__device__ __forceinline__ float gelu_exact(float v) {
    return 0.5f * v * (1.0f + erff(v * 0.70710678118654752f));
}

// ---------------- launch 1: gating (fp32 exact) + tf32-round x (permuted) ----------------
__global__ __launch_bounds__(256) void gate_kernel(const float* __restrict__ x,
                                                   const float* __restrict__ Wg,
                                                   const float* __restrict__ bg) {
    int t = blockIdx.x * 8 + (threadIdx.x >> 5);
    int lane = threadIdx.x & 31;
    if (t >= T_TOK) return;
    float acc[E_NUM];
#pragma unroll
    for (int e = 0; e < E_NUM; e++) acc[e] = 0.0f;
    const float* xp = x + (size_t)t * D_DIM;
    float* xr = g_Xr + (size_t)t * D_DIM;
    for (int k = lane; k < D_DIM; k += 32) {
        float xv = xp[k];
        xr[perm8(k)] = tf32r(xv);                // fused permuted tf32 pass
        const float4 w0 = *(const float4*)(Wg + (size_t)k * E_NUM);
        const float4 w1 = *(const float4*)(Wg + (size_t)k * E_NUM + 4);
        acc[0] += xv * w0.x; acc[1] += xv * w0.y; acc[2] += xv * w0.z; acc[3] += xv * w0.w;
        acc[4] += xv * w1.x; acc[5] += xv * w1.y; acc[6] += xv * w1.z; acc[7] += xv * w1.w;
    }
#pragma unroll
    for (int e = 0; e < E_NUM; e++)
#pragma unroll
        for (int o = 16; o > 0; o >>= 1)
            acc[e] += __shfl_down_sync(0xffffffffu, acc[e], o);
    if (lane == 0) {
        float mx = -1e30f;
#pragma unroll
        for (int e = 0; e < E_NUM; e++) { acc[e] += bg[e]; mx = fmaxf(mx, acc[e]); }
        float s = 0.0f, p[E_NUM];
#pragma unroll
        for (int e = 0; e < E_NUM; e++) { p[e] = expf(acc[e] - mx); s += p[e]; }
        float inv = 1.0f / s;
        float best = -1.0f; int bi = 0;
#pragma unroll
        for (int e = 0; e < E_NUM; e++) {
            float pe = p[e] * inv;
            if (pe > best) { best = pe; bi = e; }
        }
        g_eidx[t] = bi;
        g_wgt[t] = best;
    }
}

// ---------------- launch 2: counts + offsets + loss (one block) ----------------
__global__ __launch_bounds__(256) void count_scan_kernel(float* __restrict__ out,
                                                         int write_loss) {
    __shared__ int cnt[E_NUM];
    __shared__ float ssum[E_NUM];
    int tid = threadIdx.x;
    if (tid < E_NUM) { cnt[tid] = 0; ssum[tid] = 0.0f; }
    __syncthreads();
    for (int t = tid; t < T_TOK; t += 256) {
        int e = g_eidx[t];
        atomicAdd(&cnt[e], 1);
        atomicAdd(&ssum[e], g_wgt[t]);
    }
    __syncthreads();
    if (tid == 0) {
        int off = 0;
        float loss = 0.0f;
#pragma unroll
        for (int e = 0; e < E_NUM; e++) {
            g_cnti[e] = cnt[e];
            g_off[e] = off;
            g_cursor[e] = 0;
            off += cnt[e];
            float usage = ssum[e] / ((float)cnt[e] + 1e-8f);
            float d = usage - 1.0f / (float)E_NUM;
            loss += d * d;
        }
        if (write_loss) out[(size_t)T_TOK * D_DIM] = loss;
    }
}

// ---------------- launch 3: scatter ----------------
__global__ void scatter_kernel() {
    int t = blockIdx.x * blockDim.x + threadIdx.x;
    if (t >= T_TOK) return;
    int e = g_eidx[t];
    int pos = atomicAdd(&g_cursor[e], 1);
    g_tok[g_off[e] + pos] = t;
}

// ================= launch 4: GEMM1 tokens[128] x (64 + 64 GLU cols), K=1024 =================
// 256 threads, 8 warps (2m x 4n), warp tile 64x16 dual. A in permuted-k SMEM, stride 24 floats.
#define G1_A_BYTES 12288                     // 128 rows x 96B
#define G1_B_BYTES 4608                      // 16 x 72 floats
#define G1_STAGE (G1_A_BYTES + 2 * G1_B_BYTES)   // 21504
#define G1_SMEM (4 * G1_STAGE)                   // 86016

__global__ __launch_bounds__(256, 2) void gemm1_kernel(const float* __restrict__ Wfc,
                                                       const float* __restrict__ bfc) {
    extern __shared__ __align__(128) char smem_raw[];
    uint32_t sb = smem_u32(smem_raw);
    int e = blockIdx.z;
    int cnt = g_cnti[e];
    int row0 = blockIdx.y * 128;
    if (row0 >= cnt) return;
    int col0 = blockIdx.x * 64;
    int off = g_off[e];
    int tid = threadIdx.x, wid = tid >> 5, lane = tid & 31;
    int g = lane >> 2, t4 = lane & 3;
    int wm = wid & 1, wn = wid >> 1;   // 2 x 4; warp tile 64 x 16

    // A loaders: 512 chunks (128 rows x 4), ids tid and tid+256
    int a_r = tid >> 2, a_c = tid & 3;
    int gi0 = off + row0 + a_r;      if (gi0 > T_TOK - 1) gi0 = T_TOK - 1;
    int gi1 = off + row0 + a_r + 64; if (gi1 > T_TOK - 1) gi1 = T_TOK - 1;
    const float* asrc0 = g_Xr + (size_t)g_tok[gi0] * D_DIM + a_c * 4;
    const float* asrc1 = g_Xr + (size_t)g_tok[gi1] * D_DIM + a_c * 4;
    uint32_t adst0 = (uint32_t)(a_r * 96 + a_c * 16);
    uint32_t adst1 = (uint32_t)((a_r + 64) * 96 + a_c * 16);
    // B loaders: 256 chunks per tile
    int b_kk = tid >> 4, b_n4 = tid & 15;
    const float* bbase = Wfc + (size_t)e * D_DIM * (2 * F_DIM) +
                         (size_t)b_kk * (2 * F_DIM) + col0 + b_n4 * 4;
    uint32_t bdst = (uint32_t)(b_kk * 288 + b_n4 * 16);

#define G1_LOAD(k0, st)                                               \
    {                                                                 \
        uint32_t base = sb + (uint32_t)(st) * G1_STAGE;               \
        cp16(base + adst0, asrc0 + (k0));                             \
        cp16(base + adst1, asrc1 + (k0));                             \
        const float* bp = bbase + (size_t)(k0) * (2 * F_DIM);         \
        cp16(base + G1_A_BYTES + bdst, bp);                           \
        cp16(base + G1_A_BYTES + G1_B_BYTES + bdst, bp + F_DIM);      \
        cp_commit();                                                  \
    }

    float c1r[4][2][4], c2r[4][2][4];
#pragma unroll
    for (int mi = 0; mi < 4; mi++)
#pragma unroll
        for (int ni = 0; ni < 2; ni++)
#pragma unroll
            for (int q = 0; q < 4; q++) { c1r[mi][ni][q] = 0.0f; c2r[mi][ni][q] = 0.0f; }

    const int NCH = D_DIM / 16;  // 64
    G1_LOAD(0, 0); G1_LOAD(16, 1); G1_LOAD(32, 2);

    for (int c = 0; c < NCH; c++) {
        int st = c & 3;
        cp_wait<2>();
        __syncthreads();
        int nc = c + 3;
        if (nc < NCH) { G1_LOAD(nc * 16, nc & 3); } else { cp_commit(); }

        const uint32_t* As = (const uint32_t*)(smem_raw + st * G1_STAGE);
        const float* B1 = (const float*)(smem_raw + st * G1_STAGE + G1_A_BYTES);
        const float* B2 = (const float*)(smem_raw + st * G1_STAGE + G1_A_BYTES + G1_B_BYTES);
#pragma unroll
        for (int k8 = 0; k8 < 16; k8 += 8) {
            uint32_t af[4][4], bf1[2][2], bf2[2][2];
#pragma unroll
            for (int mi = 0; mi < 4; mi++) {
                const uint32_t* ap = As + (wm * 64 + mi * 16 + g) * 24 + k8 + t4 * 2;
                uint2 lo = *(const uint2*)ap;
                uint2 hi = *(const uint2*)(ap + 8 * 24);
                af[mi][0] = lo.x; af[mi][1] = hi.x; af[mi][2] = lo.y; af[mi][3] = hi.y;
            }
#pragma unroll
            for (int ni = 0; ni < 2; ni++) {
                int n = wn * 16 + ni * 8 + g;
                const float* bp1 = B1 + (k8 + t4) * 72 + n;
                bf1[ni][0] = cvt_tf32(bp1[0]);
                bf1[ni][1] = cvt_tf32(bp1[4 * 72]);
                const float* bp2 = B2 + (k8 + t4) * 72 + n;
                bf2[ni][0] = cvt_tf32(bp2[0]);
                bf2[ni][1] = cvt_tf32(bp2[4 * 72]);
            }
#pragma unroll
            for (int mi = 0; mi < 4; mi++)
#pragma unroll
                for (int ni = 0; ni < 2; ni++) {
                    mma8(c1r[mi][ni], af[mi], bf1[ni]);
                    mma8(c2r[mi][ni], af[mi], bf2[ni]);
                }
        }
    }
#undef G1_LOAD

    // epilogue: bias + GLU -> g_G (grouped rows, tf32-rounded, PERMUTED k-layout)
    const float* bias = bfc + (size_t)e * (2 * F_DIM);
#pragma unroll
    for (int mi = 0; mi < 4; mi++) {
        int rl = wm * 64 + mi * 16 + g;
#pragma unroll
        for (int ni = 0; ni < 2; ni++) {
            int n = col0 + wn * 16 + ni * 8 + 2 * t4;
            int p0 = perm8(n), p1 = perm8(n + 1);
            float b1a = bias[n], b1b = bias[n + 1];
            float b2a = bias[F_DIM + n], b2b = bias[F_DIM + n + 1];
            if (row0 + rl < cnt) {
                float h1 = c1r[mi][ni][0] + b1a, h2 = c2r[mi][ni][0] + b2a;
                float u1 = c1r[mi][ni][1] + b1b, u2 = c2r[mi][ni][1] + b2b;
                float* gp = g_G + (size_t)(off + row0 + rl) * F_DIM;
                gp[p0] = tf32r(h1 * gelu_exact(h2));
                gp[p1] = tf32r(u1 * gelu_exact(u2));
            }
            if (row0 + rl + 8 < cnt) {
                float h1 = c1r[mi][ni][2] + b1a, h2 = c2r[mi][ni][2] + b2a;
                float u1 = c1r[mi][ni][3] + b1b, u2 = c2r[mi][ni][3] + b2b;
                float* gp = g_G + (size_t)(off + row0 + rl + 8) * F_DIM;
                gp[p0] = tf32r(h1 * gelu_exact(h2));
                gp[p1] = tf32r(u1 * gelu_exact(u2));
            }
        }
    }
}

// ================= launch 5: GEMM2 rows[128] x 64 D cols, K=4096 =================
#define G2_A_BYTES 12288
#define G2_B_BYTES 4608
#define G2_STAGE (G2_A_BYTES + G2_B_BYTES)   // 16896
#define G2_SMEM (4 * G2_STAGE)               // 67584

__global__ __launch_bounds__(256, 2) void gemm2_kernel(const float* __restrict__ Wout,
                                                       const float* __restrict__ bout,
                                                       float* __restrict__ out) {
    extern __shared__ __align__(128) char smem_raw[];
    uint32_t sb = smem_u32(smem_raw);
    int e = blockIdx.z;
    int cnt = g_cnti[e];
    int row0 = blockIdx.y * 128;
    if (row0 >= cnt) return;
    int col0 = blockIdx.x * 64;
    int off = g_off[e];
    int tid = threadIdx.x, wid = tid >> 5, lane = tid & 31;
    int g = lane >> 2, t4 = lane & 3;
    int wm = wid & 1, wn = wid >> 1;

    int a_r = tid >> 2, a_c = tid & 3;
    int gi0 = off + row0 + a_r;      if (gi0 > T_TOK - 1) gi0 = T_TOK - 1;
    int gi1 = off + row0 + a_r + 64; if (gi1 > T_TOK - 1) gi1 = T_TOK - 1;
    const float* asrc0 = g_G + (size_t)gi0 * F_DIM + a_c * 4;
    const float* asrc1 = g_G + (size_t)gi1 * F_DIM + a_c * 4;
    uint32_t adst0 = (uint32_t)(a_r * 96 + a_c * 16);
    uint32_t adst1 = (uint32_t)((a_r + 64) * 96 + a_c * 16);
    int b_kk = tid >> 4, b_n4 = tid & 15;
    const float* bbase = Wout + (size_t)e * F_DIM * D_DIM +
                         (size_t)b_kk * D_DIM + col0 + b_n4 * 4;
    uint32_t bdst = (uint32_t)(b_kk * 288 + b_n4 * 16);

#define G2_LOAD(k0, st)                                               \
    {                                                                 \
        uint32_t base = sb + (uint32_t)(st) * G2_STAGE;               \
        cp16(base + adst0, asrc0 + (k0));                             \
        cp16(base + adst1, asrc1 + (k0));                             \
        cp16(base + G2_A_BYTES + bdst, bbase + (size_t)(k0) * D_DIM); \
        cp_commit();                                                  \
    }

    float cr[4][2][4];
#pragma unroll
    for (int mi = 0; mi < 4; mi++)
#pragma unroll
        for (int ni = 0; ni < 2; ni++)
#pragma unroll
            for (int q = 0; q < 4; q++) cr[mi][ni][q] = 0.0f;

    const int NCH = F_DIM / 16;  // 256
    G2_LOAD(0, 0); G2_LOAD(16, 1); G2_LOAD(32, 2);

    for (int c = 0; c < NCH; c++) {
        int st = c & 3;
        cp_wait<2>();
        __syncthreads();
        int nc = c + 3;
        if (nc < NCH) { G2_LOAD(nc * 16, nc & 3); } else { cp_commit(); }

        const uint32_t* As = (const uint32_t*)(smem_raw + st * G2_STAGE);
        const float* Bs = (const float*)(smem_raw + st * G2_STAGE + G2_A_BYTES);
#pragma unroll
        for (int k8 = 0; k8 < 16; k8 += 8) {
            uint32_t af[4][4], bf[2][2];
#pragma unroll
            for (int mi = 0; mi < 4; mi++) {
                const uint32_t* ap = As + (wm * 64 + mi * 16 + g) * 24 + k8 + t4 * 2;
                uint2 lo = *(const uint2*)ap;
                uint2 hi = *(const uint2*)(ap + 8 * 24);
                af[mi][0] = lo.x; af[mi][1] = hi.x; af[mi][2] = lo.y; af[mi][3] = hi.y;
            }
#pragma unroll
            for (int ni = 0; ni < 2; ni++) {
                int n = wn * 16 + ni * 8 + g;
                const float* bp = Bs + (k8 + t4) * 72 + n;
                bf[ni][0] = cvt_tf32(bp[0]);
                bf[ni][1] = cvt_tf32(bp[4 * 72]);
            }
#pragma unroll
            for (int mi = 0; mi < 4; mi++)
#pragma unroll
                for (int ni = 0; ni < 2; ni++)
                    mma8(cr[mi][ni], af[mi], bf[ni]);
        }
    }
#undef G2_LOAD

    const float* bias = bout + (size_t)e * D_DIM;
#pragma unroll
    for (int mi = 0; mi < 4; mi++) {
        int rl = wm * 64 + mi * 16 + g;
#pragma unroll
        for (int ni = 0; ni < 2; ni++) {
            int n = col0 + wn * 16 + ni * 8 + 2 * t4;
            float ba = bias[n], bb = bias[n + 1];
            if (row0 + rl < cnt) {
                int tok = g_tok[off + row0 + rl];
                float w = g_wgt[tok];
                float2 v = make_float2(w * (cr[mi][ni][0] + ba),
                                       w * (cr[mi][ni][1] + bb));
                *(float2*)(out + (size_t)tok * D_DIM + n) = v;
            }
            if (row0 + rl + 8 < cnt) {
                int tok = g_tok[off + row0 + rl + 8];
                float w = g_wgt[tok];
                float2 v = make_float2(w * (cr[mi][ni][2] + ba),
                                       w * (cr[mi][ni][3] + bb));
                *(float2*)(out + (size_t)tok * D_DIM + n) = v;
            }
        }
    }
}

// ---------------- launch ----------------
extern "C" void kernel_launch(void* const* d_in, const int* in_sizes, int n_in,
                              void* d_out, int out_size) {
    const float* x    = (const float*)d_in[0];
    const float* Wg   = (const float*)d_in[1];
    const float* bg   = (const float*)d_in[2];
    const float* Wfc  = (const float*)d_in[3];
    const float* bfc  = (const float*)d_in[4];
    const float* Wout = (const float*)d_in[5];
    const float* bout = (const float*)d_in[6];
    float* out = (float*)d_out;
    int write_loss = (out_size > T_TOK * D_DIM) ? 1 : 0;

    cudaFuncSetAttribute(gemm1_kernel, cudaFuncAttributeMaxDynamicSharedMemorySize, G1_SMEM);
    cudaFuncSetAttribute(gemm2_kernel, cudaFuncAttributeMaxDynamicSharedMemorySize, G2_SMEM);

    gate_kernel<<<T_TOK / 8, 256>>>(x, Wg, bg);          // launch 1
    count_scan_kernel<<<1, 256>>>(out, write_loss);      // launch 2
    scatter_kernel<<<T_TOK / 256, 256>>>();              // launch 3
    {
        dim3 grid(F_DIM / 64, T_TOK / 128, E_NUM);
        gemm1_kernel<<<grid, 256, G1_SMEM>>>(Wfc, bfc);  // launch 4 (profiled)
    }
    {
        dim3 grid(D_DIM / 64, T_TOK / 128, E_NUM);
        gemm2_kernel<<<grid, 256, G2_SMEM>>>(Wout, bout, out);  // launch 5
    }
}